// round 6
// baseline (speedup 1.0000x reference)
#include <cuda_runtime.h>
#include <cstdint>

#define B_SZ  8
#define SEQ   4096
#define HID   1024
#define NGRP  (SEQ / 32)     // 128 t-groups of 32 steps
#define DMAX  64             // FIR truncation: g[d] ~ 0.16^d
#define CHUNKS 4             // time-chunks for the SNN scan
#define CGRP   (NGRP / CHUNKS)  // 32 stored groups per chunk
#define WGRP   8             // warmup groups (256 steps): 0.9^256 ~ 2e-12
#define YC     256           // t-chunk per fused u+y block

// ---------------- scratch (device globals; no allocation allowed) ----------------
// bit (t&31) of word [b][t>>5][h] = spike(b,t,h). 4 MB.
__device__ unsigned g_bits[B_SZ][NGRP][HID];
__device__ float    g_g[DMAX];          // impulse response C A^d B
__device__ float    g_y[B_SZ][SEQ];     // y[b][t]

// ---------------- LIF step: float-mask form, 12-cycle dependent chain ------------
// State: w09 = rn(0.9 * v_pre-reset), ns = 1 - spike_prev, act = (r <= 0), r.
// All masks are exactly 0.0/1.0 so every FFMA reproduces the reference's
// separate mul+add rounding exactly. r stays an exact small integer in fp32.
struct SnnState { float w09, ns, act, r; };

__device__ __forceinline__ void snn_step(SnnState& st, float xk,
                                         unsigned& mask, unsigned bit)
{
    float v1 = __fmaf_rn(st.w09, st.ns, xk);          // rn(0.9*v_post + x)
    float ge; asm("set.ge.f32.f32 %0, %1, %2;" : "=f"(ge) : "f"(v1), "f"(1.0f));
    float s  = __fmul_rn(ge, st.act);                 // spike as 0.0/1.0
    st.w09   = __fmul_rn(v1, 0.9f);
    st.ns    = __fmaf_rn(-ge, st.act, 1.0f);          // 1 - spike (exact)
    float rd = fmaxf(__fadd_rn(st.r, -1.0f), 0.0f);   // max(r-1,0), exact
    st.r     = __fmaf_rn(s, 5.0f, rd);                // spike => rd==0 => 5
    asm("set.le.f32.f32 %0, %1, %2;" : "=f"(st.act) : "f"(st.r), "f"(0.0f));
    if (s != 0.0f) mask |= bit;                       // off critical path
}

// ---------------- pass 1: LIF neurons -> spike bitmasks (+hidden g block) --------
__global__ void __launch_bounds__(64) snn_kernel(const float* __restrict__ x,
                                                 const float* __restrict__ Ap,
                                                 const float* __restrict__ Bp,
                                                 const float* __restrict__ Cp)
{
    __shared__ float As[64 * 65];
    __shared__ float ws[64];
    __shared__ float red[2];

    if (blockIdx.x >= B_SZ * 16 * CHUNKS) {
        // ---- g block: g[d] = C . (A^d B), d = 0..63 ----
        const int tid = threadIdx.x;      // 64 threads, state index n = tid
        for (int i = tid; i < 64 * 64; i += 64)
            As[(i >> 6) * 65 + (i & 63)] = Ap[i];
        const float cv = Cp[tid];
        float w = Bp[tid];
        ws[tid] = w;
        __syncthreads();
        for (int d = 0; d < DMAX; d++) {
            float p = cv * w;
            #pragma unroll
            for (int o = 16; o; o >>= 1) p += __shfl_down_sync(0xffffffffu, p, o);
            if ((tid & 31) == 0) red[tid >> 5] = p;
            __syncthreads();
            if (tid == 0) g_g[d] = red[0] + red[1];
            if (d < DMAX - 1) {
                float a0 = 0.f, a1 = 0.f, a2 = 0.f, a3 = 0.f;
                #pragma unroll
                for (int s = 0; s < 64; s += 4) {
                    a0 += As[tid * 65 + s + 0] * ws[s + 0];
                    a1 += As[tid * 65 + s + 1] * ws[s + 1];
                    a2 += As[tid * 65 + s + 2] * ws[s + 2];
                    a3 += As[tid * 65 + s + 3] * ws[s + 3];
                }
                float wn = (a0 + a1) + (a2 + a3);
                __syncthreads();
                ws[tid] = wn;
                __syncthreads();
                w = wn;
            }
        }
        return;
    }

    // ---- SNN path: one thread = one (b,h) lane over one time-chunk ----
    const int blk  = blockIdx.x;               // 0..511
    const int c    = blk & (CHUNKS - 1);
    const int hblk = (blk >> 2) & 15;
    const int b    = blk >> 6;
    const int tid  = threadIdx.x;
    const int h    = hblk * 64 + tid;

    const int warm    = (c == 0) ? 0 : WGRP;
    const int g0      = c * CGRP;              // first stored group
    const int tbegin  = g0 * 32 - warm * 32;
    const int ngroups = warm + CGRP;           // 32 or 40: always even

    const float* xp = x + ((size_t)b * SEQ + tbegin) * HID + h;
    unsigned* sbw = &g_bits[b][g0][h];

    // double buffer, distance-2 group prefetch (~64 steps ahead > DRAM latency).
    // #pragma unroll 2 makes (gg & 1) compile-time in both copies -> no local mem.
    float xbuf[2][32];
    const float* xld = xp;
    #pragma unroll
    for (int i = 0; i < 32; i++) xbuf[0][i] = xld[(size_t)i * HID];
    xld += 32 * HID;
    #pragma unroll
    for (int i = 0; i < 32; i++) xbuf[1][i] = xld[(size_t)i * HID];
    xld += 32 * HID;

    SnnState st = {0.0f, 1.0f, 1.0f, 0.0f};

    #pragma unroll 2
    for (int gg = 0; gg < ngroups; gg++) {
        const bool pf = (gg + 2 < ngroups);
        unsigned mask = 0;
        #pragma unroll
        for (int i = 0; i < 32; i++) {
            float xk = xbuf[gg & 1][i];
            if (pf) xbuf[gg & 1][i] = xld[(size_t)i * HID];  // prefetch gg+2
            snn_step(st, xk, mask, 1u << i);
        }
        xld += 32 * HID;
        if (gg >= warm) { *sbw = mask; sbw += HID; }         // coalesced
    }
}

// ---------------- pass 2: fused u (popcount transpose) + y (64-tap FIR) ----------
// grid: B_SZ*16 blocks, 256 threads; block (b,yc) produces y[b][yc*256 .. +256).
__global__ void __launch_bounds__(256) uy_kernel(const float* __restrict__ Dp)
{
    __shared__ unsigned wsm[HID];
    __shared__ int   part[8 * 32];
    __shared__ float u_s[64 + YC];   // u_s[i] = u[t0 - 64 + i]
    __shared__ float g_s[DMAX];

    const int b   = blockIdx.x >> 4;
    const int yc  = blockIdx.x & 15;
    const int t0  = yc * YC;
    const int gb  = yc * (YC / 32);
    const int tid = threadIdx.x;
    const int wid = tid >> 5, lane = tid & 31;

    if (tid < DMAX) g_s[tid] = g_g[tid];

    for (int j = -2; j < YC / 32; j++) {        // 2 halo groups + 8 own groups
        const int g  = gb + j;
        const int i0 = 64 + j * 32;
        if (g < 0) {
            if (tid < 32) u_s[i0 + tid] = 0.0f;
            continue;
        }
        ((uint4*)wsm)[tid] = ((const uint4*)&g_bits[b][g][0])[tid];
        __syncthreads();
        int cnt = 0;
        #pragma unroll 8
        for (int i2 = 0; i2 < 128; i2++)
            cnt += (int)((wsm[wid * 128 + i2] >> lane) & 1u);
        part[wid * 32 + lane] = cnt;
        __syncthreads();
        if (tid < 32) {
            int tot = 0;
            #pragma unroll
            for (int ww = 0; ww < 8; ww++) tot += part[ww * 32 + tid];
            u_s[i0 + tid] = (float)tot * (1.0f / (float)HID);
        }
        __syncthreads();
    }

    const float Ds = *Dp;
    {
        const int i = tid;                      // YC == blockDim.x
        float acc = Ds * u_s[64 + i];
        #pragma unroll
        for (int d = 0; d < DMAX; d++)
            acc += g_s[d] * u_s[64 + i - d];
        g_y[b][t0 + i] = acc;
    }
}

// ---------------- pass 3: out[b][t][h] = spike_bit + y[b][t] ---------------------
// grid: B_SZ * NGRP * 2 blocks; block covers 16 t x 1024 h (64 KB of output).
__global__ void __launch_bounds__(256) out_kernel(float4* __restrict__ out)
{
    __shared__ float ys[16], ys1[16];

    const int blk  = blockIdx.x;
    const int half = blk & 1;
    const int g    = (blk >> 1) & (NGRP - 1);
    const int b    = blk >> 8;
    const int tid  = threadIdx.x;            // h4 = tid: hidden 4*tid..4*tid+3

    if (tid < 16) {
        float yv = g_y[b][g * 32 + half * 16 + tid];
        ys[tid]  = yv;
        ys1[tid] = yv + 1.0f;
    }
    const uint4 wv = ((const uint4*)&g_bits[b][g][0])[tid];
    __syncthreads();

    float4* base = out + ((size_t)(b * SEQ + g * 32 + half * 16) * HID) / 4 + tid;
    #pragma unroll
    for (int t = 0; t < 16; t++) {
        const unsigned bit = 1u << (half * 16 + t);
        const float y  = ys[t];
        const float y1 = ys1[t];
        float4 o;
        o.x = (wv.x & bit) ? y1 : y;
        o.y = (wv.y & bit) ? y1 : y;
        o.z = (wv.z & bit) ? y1 : y;
        o.w = (wv.w & bit) ? y1 : y;
        __stcs(&base[(size_t)t * (HID / 4)], o);
    }
}

// ---------------- launch ----------------------------------------------------------
extern "C" void kernel_launch(void* const* d_in, const int* in_sizes, int n_in,
                              void* d_out, int out_size)
{
    const float* x  = (const float*)d_in[0];   // (8, 4096, 1024) f32
    const float* A  = (const float*)d_in[1];   // (64, 64)
    const float* Bv = (const float*)d_in[2];   // (64, 1)
    const float* Cv = (const float*)d_in[3];   // (1, 64)
    const float* Dp = (const float*)d_in[4];   // (1, 1)

    snn_kernel<<<B_SZ * 16 * CHUNKS + 1, 64>>>(x, A, Bv, Cv);
    uy_kernel<<<B_SZ * 16, 256>>>(Dp);
    out_kernel<<<B_SZ * NGRP * 2, 256>>>((float4*)d_out);
}

// round 7
// speedup vs baseline: 1.1025x; 1.1025x over previous
#include <cuda_runtime.h>
#include <cstdint>

#define B_SZ  8
#define SEQ   4096
#define HID   1024
#define NGRP  (SEQ / 32)     // 128 t-groups of 32 steps
#define DMAX  64             // FIR truncation: g[d] ~ 0.16^d
#define CHUNKS 8             // time-chunks for the SNN scan
#define CGRP   (NGRP / CHUNKS)  // 16 stored groups per chunk
#define WGRP   8             // warmup groups (256 steps): 0.9^256 ~ 2e-12
#define YC     256           // t-chunk per fused u+y block

// ---------------- scratch (device globals; no allocation allowed) ----------------
// bit (t&31) of word [b][t>>5][h] = spike(b,t,h). 4 MB.
__device__ unsigned g_bits[B_SZ][NGRP][HID];
__device__ float    g_g[DMAX];          // impulse response C A^d B
__device__ float    g_y[B_SZ][SEQ];     // y[b][t]

// ---------------- LIF step: float-mask form, ~12-cycle dependent chain -----------
// State: w09 = rn(0.9 * v_pre-reset), ns = 1 - spike_prev, act = (r <= 0), r.
// All masks are exactly 0.0/1.0 so every FFMA reproduces the reference's
// separate mul+add rounding exactly. r stays an exact small integer in fp32.
struct SnnState { float w09, ns, act, r; };

__device__ __forceinline__ void snn_step(SnnState& st, float xk,
                                         float& macc, float mc)
{
    float v1 = __fmaf_rn(st.w09, st.ns, xk);          // rn(0.9*v_post + x)
    float ge; asm("set.ge.f32.f32 %0, %1, %2;" : "=f"(ge) : "f"(v1), "f"(1.0f));
    float s  = __fmul_rn(ge, st.act);                 // spike as 0.0/1.0
    st.w09   = __fmul_rn(v1, 0.9f);
    st.ns    = __fmaf_rn(-ge, st.act, 1.0f);          // 1 - spike (exact)
    float rd = fmaxf(__fadd_rn(st.r, -1.0f), 0.0f);   // max(r-1,0), exact
    st.r     = __fmaf_rn(s, 5.0f, rd);                // spike => rd==0 => 5
    asm("set.le.f32.f32 %0, %1, %2;" : "=f"(st.act) : "f"(st.r), "f"(0.0f));
    macc     = __fmaf_rn(s, mc, macc);                // exact bit accumulation
}

// ---------------- pass 1: LIF neurons -> spike bitmasks (+hidden g block) --------
// 512 snn blocks of 128 threads: (b, hblk, chunk); one thread = one (b,h) lane
// over one time-chunk (256-step warmup). Last block computes g[d] = C A^d B.
__global__ void __launch_bounds__(128) snn_kernel(const float* __restrict__ x,
                                                  const float* __restrict__ Ap,
                                                  const float* __restrict__ Bp,
                                                  const float* __restrict__ Cp)
{
    __shared__ float As[64 * 65];
    __shared__ float ws[64];
    __shared__ float red[2];

    if (blockIdx.x >= B_SZ * 8 * CHUNKS) {
        // ---- g block: g[d] = C . (A^d B), d = 0..63 (tid<64 active) ----
        const int tid = threadIdx.x;
        for (int i = tid; i < 64 * 64; i += 128)
            As[(i >> 6) * 65 + (i & 63)] = Ap[i];
        float cv = 0.f, w = 0.f;
        if (tid < 64) {
            cv = Cp[tid];
            w  = Bp[tid];
            ws[tid] = w;
        }
        __syncthreads();
        for (int d = 0; d < DMAX; d++) {
            if (tid < 64) {
                float p = cv * w;
                #pragma unroll
                for (int o = 16; o; o >>= 1) p += __shfl_down_sync(0xffffffffu, p, o);
                if ((tid & 31) == 0) red[tid >> 5] = p;
            }
            __syncthreads();
            if (tid == 0) g_g[d] = red[0] + red[1];
            if (d < DMAX - 1) {
                float wn = 0.f;
                if (tid < 64) {
                    float a0 = 0.f, a1 = 0.f, a2 = 0.f, a3 = 0.f;
                    #pragma unroll
                    for (int s = 0; s < 64; s += 4) {
                        a0 += As[tid * 65 + s + 0] * ws[s + 0];
                        a1 += As[tid * 65 + s + 1] * ws[s + 1];
                        a2 += As[tid * 65 + s + 2] * ws[s + 2];
                        a3 += As[tid * 65 + s + 3] * ws[s + 3];
                    }
                    wn = (a0 + a1) + (a2 + a3);
                }
                __syncthreads();
                if (tid < 64) ws[tid] = wn;
                __syncthreads();
                w = wn;
            }
        }
        return;
    }

    // ---- SNN path ----
    const int blk  = blockIdx.x;               // 0..511
    const int c    = blk & (CHUNKS - 1);
    const int hblk = (blk >> 3) & 7;
    const int b    = blk >> 6;
    const int tid  = threadIdx.x;
    const int h    = hblk * 128 + tid;

    const int warm    = (c == 0) ? 0 : WGRP;
    const int g0      = c * CGRP;              // first stored group
    const int tbegin  = g0 * 32 - warm * 32;
    const int ngroups = warm + CGRP;           // 16 or 24

    const float* xp = x + ((size_t)b * SEQ + tbegin) * HID + h;
    unsigned* sbw = &g_bits[b][g0][h];

    // single 32-register buffer, constant indices only (no local-mem demotion);
    // value loaded at (gg,i) is consumed at (gg+1,i): 32-step prefetch distance.
    float xbuf[32];
    #pragma unroll
    for (int i = 0; i < 32; i++) xbuf[i] = xp[(size_t)i * HID];
    const float* xld = xp + 32 * HID;

    SnnState st = {0.0f, 1.0f, 1.0f, 0.0f};

    for (int gg = 0; gg < ngroups; gg++) {
        const bool pf = (gg + 1 < ngroups);
        float mlo = 0.0f, mhi = 0.0f;
        #pragma unroll
        for (int i = 0; i < 32; i++) {
            float xk = xbuf[i];
            if (pf) xbuf[i] = xld[(size_t)i * HID];    // prefetch next group
            if (i < 16) snn_step(st, xk, mlo, (float)(1u << i));
            else        snn_step(st, xk, mhi, (float)(1u << (i - 16)));
        }
        xld += 32 * HID;
        unsigned mask = __float2uint_rn(mlo) | (__float2uint_rn(mhi) << 16);
        if (gg >= warm) { *sbw = mask; sbw += HID; }   // coalesced
    }
}

// ---------------- pass 2: fused u (popcount transpose) + y (64-tap FIR) ----------
// grid: B_SZ*16 blocks, 256 threads; block (b,yc) produces y[b][yc*256 .. +256).
__global__ void __launch_bounds__(256) uy_kernel(const float* __restrict__ Dp)
{
    __shared__ unsigned wsm[HID];
    __shared__ int   part[8 * 32];
    __shared__ float u_s[64 + YC];   // u_s[i] = u[t0 - 64 + i]
    __shared__ float g_s[DMAX];

    const int b   = blockIdx.x >> 4;
    const int yc  = blockIdx.x & 15;
    const int t0  = yc * YC;
    const int gb  = yc * (YC / 32);
    const int tid = threadIdx.x;
    const int wid = tid >> 5, lane = tid & 31;

    if (tid < DMAX) g_s[tid] = g_g[tid];

    for (int j = -2; j < YC / 32; j++) {        // 2 halo groups + 8 own groups
        const int g  = gb + j;
        const int i0 = 64 + j * 32;
        if (g < 0) {
            if (tid < 32) u_s[i0 + tid] = 0.0f;
            continue;
        }
        ((uint4*)wsm)[tid] = ((const uint4*)&g_bits[b][g][0])[tid];
        __syncthreads();
        int cnt = 0;
        #pragma unroll 8
        for (int i2 = 0; i2 < 128; i2++)
            cnt += (int)((wsm[wid * 128 + i2] >> lane) & 1u);
        part[wid * 32 + lane] = cnt;
        __syncthreads();
        if (tid < 32) {
            int tot = 0;
            #pragma unroll
            for (int ww = 0; ww < 8; ww++) tot += part[ww * 32 + tid];
            u_s[i0 + tid] = (float)tot * (1.0f / (float)HID);
        }
        __syncthreads();
    }

    const float Ds = *Dp;
    {
        const int i = tid;                      // YC == blockDim.x
        float acc = Ds * u_s[64 + i];
        #pragma unroll
        for (int d = 0; d < DMAX; d++)
            acc += g_s[d] * u_s[64 + i - d];
        g_y[b][t0 + i] = acc;
    }
}

// ---------------- pass 3: out[b][t][h] = spike_bit + y[b][t] ---------------------
// grid: B_SZ * NGRP * 2 blocks; block covers 16 t x 1024 h (64 KB of output).
__global__ void __launch_bounds__(256) out_kernel(float4* __restrict__ out)
{
    __shared__ float ys[16], ys1[16];

    const int blk  = blockIdx.x;
    const int half = blk & 1;
    const int g    = (blk >> 1) & (NGRP - 1);
    const int b    = blk >> 8;
    const int tid  = threadIdx.x;            // h4 = tid: hidden 4*tid..4*tid+3

    if (tid < 16) {
        float yv = g_y[b][g * 32 + half * 16 + tid];
        ys[tid]  = yv;
        ys1[tid] = yv + 1.0f;
    }
    const uint4 wv = ((const uint4*)&g_bits[b][g][0])[tid];
    __syncthreads();

    float4* base = out + ((size_t)(b * SEQ + g * 32 + half * 16) * HID) / 4 + tid;
    #pragma unroll
    for (int t = 0; t < 16; t++) {
        const unsigned bit = 1u << (half * 16 + t);
        const float y  = ys[t];
        const float y1 = ys1[t];
        float4 o;
        o.x = (wv.x & bit) ? y1 : y;
        o.y = (wv.y & bit) ? y1 : y;
        o.z = (wv.z & bit) ? y1 : y;
        o.w = (wv.w & bit) ? y1 : y;
        __stcs(&base[(size_t)t * (HID / 4)], o);
    }
}

// ---------------- launch ----------------------------------------------------------
extern "C" void kernel_launch(void* const* d_in, const int* in_sizes, int n_in,
                              void* d_out, int out_size)
{
    const float* x  = (const float*)d_in[0];   // (8, 4096, 1024) f32
    const float* A  = (const float*)d_in[1];   // (64, 64)
    const float* Bv = (const float*)d_in[2];   // (64, 1)
    const float* Cv = (const float*)d_in[3];   // (1, 64)
    const float* Dp = (const float*)d_in[4];   // (1, 1)

    snn_kernel<<<B_SZ * 8 * CHUNKS + 1, 128>>>(x, A, Bv, Cv);
    uy_kernel<<<B_SZ * 16, 256>>>(Dp);
    out_kernel<<<B_SZ * NGRP * 2, 256>>>((float4*)d_out);
}